// round 13
// baseline (speedup 1.0000x reference)
#include <cuda_runtime.h>
#include <cuda_fp16.h>
#include <cstdint>

// ---------------------------------------------------------------------------
// Problem constants
// ---------------------------------------------------------------------------
#define B_ROWS 4096
#define D_DIM  512
#define C_DIM  20000

#define BM 128
#define BN 128
#define BK 64                   // 64 fp16 = 128B rows (SW128 atom)
#define NK (D_DIM / BK)         // 8 k-iterations
#define STAGES 3
#define THREADS 256

#define STAGE_BYTES ((BM + BN) * BK * 2)   // 32768
#define SMEM_BYTES  (STAGES * STAGE_BYTES + 1024)

static __device__ __half g_f16[(size_t)B_ROWS * D_DIM];   // normalized feat, fp16
static __device__ __half g_w16[(size_t)C_DIM * D_DIM];    // normalized weights, fp16

// ArcFace constants
#define AF_SCALE  30.0f
#define AF_COSM   0.87758256189037271612f   // cos(0.5)
#define AF_SINM   0.47942553860420300027f   // sin(0.5)
#define AF_THRESH (-0.87758256189037271612f)
#define AF_EXTV   (-0.23971276930210150013f) // -0.5*sin(0.5)

// ---------------------------------------------------------------------------
// PTX helpers
// ---------------------------------------------------------------------------
__device__ __forceinline__ uint32_t smem_u32(const void* p) {
    uint32_t a;
    asm("{ .reg .u64 t; cvta.to.shared.u64 t, %1; cvt.u32.u64 %0, t; }"
        : "=r"(a) : "l"(p));
    return a;
}

__device__ __forceinline__ void cp16(uint32_t dst, const void* src) {
    asm volatile("cp.async.cg.shared.global [%0], [%1], 16;"
                 :: "r"(dst), "l"(src));
}
__device__ __forceinline__ void cp16z(uint32_t dst, const void* src,
                                      uint32_t ssize) {
    asm volatile("cp.async.cg.shared.global [%0], [%1], 16, %2;"
                 :: "r"(dst), "l"(src), "r"(ssize));
}
#define CP_COMMIT() asm volatile("cp.async.commit_group;" ::: "memory")
#define CP_WAIT(n)  asm volatile("cp.async.wait_group %0;" :: "n"(n) : "memory")

#define LDSM_X4(r, addr) \
    asm volatile("ldmatrix.sync.aligned.m8n8.x4.shared.b16 {%0,%1,%2,%3}, [%4];" \
        : "=r"((r)[0]), "=r"((r)[1]), "=r"((r)[2]), "=r"((r)[3]) : "r"(addr))

// fp16-accumulate MMA: D(+)= A*B + C, C/D are 2 b32 regs (4 halves)
__device__ __forceinline__ void mma_f16acc(uint32_t* d, const uint32_t* a,
                                           uint32_t b0, uint32_t b1) {
    asm volatile(
        "mma.sync.aligned.m16n8k16.row.col.f16.f16.f16.f16 "
        "{%0,%1}, {%2,%3,%4,%5}, {%6,%7}, {%0,%1};"
        : "+r"(d[0]), "+r"(d[1])
        : "r"(a[0]), "r"(a[1]), "r"(a[2]), "r"(a[3]), "r"(b0), "r"(b1));
}
// first step of each chunk: C = 0 (no zeroing movs needed)
__device__ __forceinline__ void mma_f16acc_z(uint32_t* d, const uint32_t* a,
                                             uint32_t b0, uint32_t b1) {
    asm volatile(
        "mma.sync.aligned.m16n8k16.row.col.f16.f16.f16.f16 "
        "{%0,%1}, {%2,%3,%4,%5}, {%6,%7}, {%8,%9};"
        : "=r"(d[0]), "=r"(d[1])
        : "r"(a[0]), "r"(a[1]), "r"(a[2]), "r"(a[3]), "r"(b0), "r"(b1),
          "r"(0u), "r"(0u));
}

__device__ __forceinline__ void st_cs_f2(float* p, float x, float y) {
    asm volatile("st.global.cs.v2.f32 [%0], {%1, %2};"
                 :: "l"(p), "f"(x), "f"(y) : "memory");
}

// ---------------------------------------------------------------------------
// Kernel 1: row L2-normalize fp32 -> fp16, both tensors in one launch
// ---------------------------------------------------------------------------
__global__ void norm_rows_kernel(const float* __restrict__ feat,
                                 const float* __restrict__ wts) {
    int row = blockIdx.x;
    const float* src;
    __half* dst;
    if (row < B_ROWS) {
        src = feat + (size_t)row * D_DIM;
        dst = g_f16 + (size_t)row * D_DIM;
    } else {
        row -= B_ROWS;
        src = wts + (size_t)row * D_DIM;
        dst = g_w16 + (size_t)row * D_DIM;
    }
    const int tid = threadIdx.x;
    const float4 v = reinterpret_cast<const float4*>(src)[tid];
    float ss = v.x * v.x + v.y * v.y + v.z * v.z + v.w * v.w;
    #pragma unroll
    for (int o = 16; o; o >>= 1) ss += __shfl_xor_sync(0xFFFFFFFFu, ss, o);
    __shared__ float ws[4];
    if ((tid & 31) == 0) ws[tid >> 5] = ss;
    __syncthreads();
    const float inv = rsqrtf(ws[0] + ws[1] + ws[2] + ws[3]);
    __half2 h0 = __floats2half2_rn(v.x * inv, v.y * inv);
    __half2 h1 = __floats2half2_rn(v.z * inv, v.w * inv);
    uint2 pk;
    pk.x = *reinterpret_cast<uint32_t*>(&h0);
    pk.y = *reinterpret_cast<uint32_t*>(&h1);
    reinterpret_cast<uint2*>(dst)[tid] = pk;
}

// ---------------------------------------------------------------------------
// ArcFace margin for the label column
// ---------------------------------------------------------------------------
__device__ __forceinline__ float af_margin(float c) {
    if (c > AF_THRESH) {
        float s = sqrtf(fmaxf(0.0f, 1.0f - c * c));
        return AF_SCALE * (c * AF_COSM - s * AF_SINM);
    }
    return AF_SCALE * (c + AF_EXTV);
}

// ---------------------------------------------------------------------------
// GEMM tile body: 128x128 CTA tile, 8 warps as 2m x 4n (warp tile 64x32),
// 3-stage cp.async pipeline, 2 CTAs/SM.
// KEY CHANGE vs R12: MMAs accumulate in FP16 within each BK=64 chunk
// (probing the half-rate-FP32-accumulate hypothesis), flushed into FP32
// master accumulators once per k-iter. Per-chunk fp16 rounding adds
// ~2-3e-4 RMS on top of the 2.9e-4 input quantization -> still < 1e-3.
// ---------------------------------------------------------------------------
template <bool FULL>
__device__ __forceinline__ void gemm_tile(const int* __restrict__ label,
                                          float* __restrict__ cos_out,
                                          float* __restrict__ marg_out,
                                          uint32_t sbase, int m0, int n0) {
    const int tid  = threadIdx.x;
    const int lane = tid & 31;
    const int wid  = tid >> 5;
    const int warp_m = wid & 1;     // 0..1  (64-row slab)
    const int warp_n = wid >> 1;    // 0..3  (32-col slab)

    // ---- loader bases (per thread) ----
    const int c16 = tid & 7;
    const int rq  = tid >> 3;
    const uint32_t dA = sbase + (uint32_t)(rq * 128 + ((c16 * 16) ^ ((rq & 7) << 4)));
    const uint32_t dB = dA + 16384;

    const __half* aSrc = g_f16 + (size_t)(m0 + rq) * D_DIM + c16 * 8;
    const __half* bSrc = nullptr;
    const __half* bSrcT[4];
    uint32_t bSz[4];
    if constexpr (FULL) {
        bSrc = g_w16 + (size_t)(n0 + rq) * D_DIM + c16 * 8;
    } else {
        #pragma unroll
        for (int i = 0; i < 4; i++) {
            int n = n0 + rq + i * 32;
            bSrcT[i] = g_w16 + (size_t)((n < C_DIM) ? n : 0) * D_DIM + c16 * 8;
            bSz[i]   = (n < C_DIM) ? 16u : 0u;
        }
    }

    // ---- ldmatrix bases ----
    const uint32_t col0 =
        ((uint32_t)((lane >> 4) * 16)) ^ ((uint32_t)((lane & 7) << 4));
    const uint32_t a_row = sbase + (uint32_t)((warp_m * 64 + (lane & 15)) * 128);
    const uint32_t b_row = sbase + 16384u + (uint32_t)((warp_n * 32 + (lane & 15)) * 128);

    float acc[4][4][4];
    #pragma unroll
    for (int mt = 0; mt < 4; mt++)
        #pragma unroll
        for (int nt = 0; nt < 4; nt++)
            #pragma unroll
            for (int e = 0; e < 4; e++) acc[mt][nt][e] = 0.0f;

    auto load_stage = [&](int st, int kk) {
        #pragma unroll
        for (int i = 0; i < 4; i++)
            cp16(dA + st * STAGE_BYTES + i * 4096, aSrc + kk + i * 16384);
        #pragma unroll
        for (int i = 0; i < 4; i++) {
            if constexpr (FULL)
                cp16(dB + st * STAGE_BYTES + i * 4096, bSrc + kk + i * 16384);
            else
                cp16z(dB + st * STAGE_BYTES + i * 4096, bSrcT[i] + kk, bSz[i]);
        }
    };

    // prologue: stages 0,1
    load_stage(0, 0);  CP_COMMIT();
    load_stage(1, BK); CP_COMMIT();

    #pragma unroll
    for (int k = 0; k < NK; k++) {
        CP_WAIT(1);
        __syncthreads();

        if (k + 2 < NK) load_stage((k + 2) % STAGES, (k + 2) * BK);
        CP_COMMIT();   // empty group in drain iters keeps wait count uniform

        const int st = (k % STAGES) * STAGE_BYTES;   // immediate under unroll
        const uint32_t aB = a_row + st;
        const uint32_t bB = b_row + st;

        uint32_t acc16[4][4][2];   // fp16 chunk accumulators (live this k-iter)

        #pragma unroll
        for (int ks = 0; ks < 4; ks++) {
            const uint32_t c = col0 ^ (uint32_t)(ks << 5);
            uint32_t a_frag[4][4];
            #pragma unroll
            for (int mt = 0; mt < 4; mt++)
                LDSM_X4(a_frag[mt], aB + c + mt * 2048);
            // B in halves: one LDSM_X4 covers 2 n-tiles; keeps b liveness at 4
            #pragma unroll
            for (int g = 0; g < 2; g++) {
                uint32_t b4[4];
                LDSM_X4(b4, bB + c + g * 2048);
                #pragma unroll
                for (int mt = 0; mt < 4; mt++)
                    #pragma unroll
                    for (int j = 0; j < 2; j++) {
                        const int nt = 2 * g + j;
                        if (ks == 0)
                            mma_f16acc_z(acc16[mt][nt], a_frag[mt],
                                         b4[j], b4[j + 2]);
                        else
                            mma_f16acc(acc16[mt][nt], a_frag[mt],
                                       b4[j], b4[j + 2]);
                    }
            }
        }

        // flush fp16 chunk sums into fp32 master accumulators
        #pragma unroll
        for (int mt = 0; mt < 4; mt++)
            #pragma unroll
            for (int nt = 0; nt < 4; nt++) {
                __half2 h0 = *reinterpret_cast<__half2*>(&acc16[mt][nt][0]);
                __half2 h1 = *reinterpret_cast<__half2*>(&acc16[mt][nt][1]);
                float2 f0 = __half22float2(h0);
                float2 f1 = __half22float2(h1);
                acc[mt][nt][0] += f0.x;
                acc[mt][nt][1] += f0.y;
                acc[mt][nt][2] += f1.x;
                acc[mt][nt][3] += f1.y;
            }
    }

    // --- fused epilogue: cos + ArcFace marginal logits, streaming stores ---
    const int mrow  = m0 + warp_m * 64 + (lane >> 2);
    const int ncol0 = n0 + warp_n * 32 + (lane & 3) * 2;
    #pragma unroll
    for (int mt = 0; mt < 4; mt++) {
        const int m1 = mrow + mt * 16;
        const int m2 = m1 + 8;
        const int lab1 = label[m1];
        const int lab2 = label[m2];
        #pragma unroll
        for (int nt = 0; nt < 4; nt++) {
            int n = ncol0 + nt * 8;
            if (!FULL && n >= C_DIM) continue;
            float c0 = acc[mt][nt][0], c1 = acc[mt][nt][1];
            float c2 = acc[mt][nt][2], c3 = acc[mt][nt][3];
            size_t o1 = (size_t)m1 * C_DIM + n;
            size_t o2 = (size_t)m2 * C_DIM + n;
            st_cs_f2(cos_out + o1, c0, c1);
            st_cs_f2(cos_out + o2, c2, c3);
            float g0 = (n     == lab1) ? af_margin(c0) : AF_SCALE * c0;
            float g1 = (n + 1 == lab1) ? af_margin(c1) : AF_SCALE * c1;
            float g2 = (n     == lab2) ? af_margin(c2) : AF_SCALE * c2;
            float g3 = (n + 1 == lab2) ? af_margin(c3) : AF_SCALE * c3;
            st_cs_f2(marg_out + o1, g0, g1);
            st_cs_f2(marg_out + o2, g2, g3);
        }
    }
}

__global__ void __launch_bounds__(THREADS, 2)
arcface_gemm_kernel(const int* __restrict__ label,
                    float* __restrict__ cos_out, float* __restrict__ marg_out) {
    extern __shared__ char dsmem[];
    const uint32_t sbase = (smem_u32(dsmem) + 1023u) & ~1023u;
    const int n0 = blockIdx.x * BN;
    const int m0 = blockIdx.y * BM;
    if (n0 + BN <= C_DIM)
        gemm_tile<true>(label, cos_out, marg_out, sbase, m0, n0);
    else
        gemm_tile<false>(label, cos_out, marg_out, sbase, m0, n0);
}

// ---------------------------------------------------------------------------
// Launch
// ---------------------------------------------------------------------------
extern "C" void kernel_launch(void* const* d_in, const int* in_sizes, int n_in,
                              void* d_out, int out_size) {
    const float* feat  = (const float*)d_in[0];
    const int*   label = (const int*)d_in[1];
    const float* wts   = (const float*)d_in[2];
    float* cos_out  = (float*)d_out;
    float* marg_out = cos_out + (size_t)B_ROWS * C_DIM;

    norm_rows_kernel<<<B_ROWS + C_DIM, 128>>>(feat, wts);

    cudaFuncSetAttribute(arcface_gemm_kernel,
                         cudaFuncAttributeMaxDynamicSharedMemorySize,
                         SMEM_BYTES);

    dim3 grid((C_DIM + BN - 1) / BN, B_ROWS / BM);   // (157, 32)
    arcface_gemm_kernel<<<grid, THREADS, SMEM_BYTES>>>(label, cos_out, marg_out);
}

// round 14
// speedup vs baseline: 1.2636x; 1.2636x over previous
#include <cuda_runtime.h>
#include <cuda_fp16.h>
#include <cstdint>

// ---------------------------------------------------------------------------
// Problem constants
// ---------------------------------------------------------------------------
#define B_ROWS 4096
#define D_DIM  512
#define C_DIM  20000

#define BM 128
#define BN 128
#define BK 64                   // 64 fp16 = 128B rows (SW128 atom)
#define NK (D_DIM / BK)         // 8 k-iterations
#define STAGES 3
#define THREADS 256

#define STAGE_BYTES ((BM + BN) * BK * 2)   // 32768
#define SMEM_BYTES  (STAGES * STAGE_BYTES + 1024)

static __device__ __half g_f16[(size_t)B_ROWS * D_DIM];   // normalized feat, fp16
static __device__ __half g_w16[(size_t)C_DIM * D_DIM];    // normalized weights, fp16

// ArcFace constants
#define AF_SCALE  30.0f
#define AF_COSM   0.87758256189037271612f   // cos(0.5)
#define AF_SINM   0.47942553860420300027f   // sin(0.5)
#define AF_THRESH (-0.87758256189037271612f)
#define AF_EXTV   (-0.23971276930210150013f) // -0.5*sin(0.5)

// ---------------------------------------------------------------------------
// PTX helpers
// ---------------------------------------------------------------------------
__device__ __forceinline__ uint32_t smem_u32(const void* p) {
    uint32_t a;
    asm("{ .reg .u64 t; cvta.to.shared.u64 t, %1; cvt.u32.u64 %0, t; }"
        : "=r"(a) : "l"(p));
    return a;
}

__device__ __forceinline__ void cp16(uint32_t dst, const void* src) {
    asm volatile("cp.async.cg.shared.global [%0], [%1], 16;"
                 :: "r"(dst), "l"(src));
}
__device__ __forceinline__ void cp16z(uint32_t dst, const void* src,
                                      uint32_t ssize) {
    asm volatile("cp.async.cg.shared.global [%0], [%1], 16, %2;"
                 :: "r"(dst), "l"(src), "r"(ssize));
}
#define CP_COMMIT() asm volatile("cp.async.commit_group;" ::: "memory")
#define CP_WAIT(n)  asm volatile("cp.async.wait_group %0;" :: "n"(n) : "memory")

#define LDSM_X4(r, addr) \
    asm volatile("ldmatrix.sync.aligned.m8n8.x4.shared.b16 {%0,%1,%2,%3}, [%4];" \
        : "=r"((r)[0]), "=r"((r)[1]), "=r"((r)[2]), "=r"((r)[3]) : "r"(addr))

__device__ __forceinline__ void mma_16816(float* d, const uint32_t* a,
                                          uint32_t b0, uint32_t b1) {
    asm volatile(
        "mma.sync.aligned.m16n8k16.row.col.f32.f16.f16.f32 "
        "{%0,%1,%2,%3}, {%4,%5,%6,%7}, {%8,%9}, {%0,%1,%2,%3};"
        : "+f"(d[0]), "+f"(d[1]), "+f"(d[2]), "+f"(d[3])
        : "r"(a[0]), "r"(a[1]), "r"(a[2]), "r"(a[3]), "r"(b0), "r"(b1));
}

__device__ __forceinline__ void st_cs_f2(float* p, float x, float y) {
    asm volatile("st.global.cs.v2.f32 [%0], {%1, %2};"
                 :: "l"(p), "f"(x), "f"(y) : "memory");
}

// ---------------------------------------------------------------------------
// Kernel 1: row L2-normalize fp32 -> fp16, both tensors in one launch
// ---------------------------------------------------------------------------
__global__ void norm_rows_kernel(const float* __restrict__ feat,
                                 const float* __restrict__ wts) {
    int row = blockIdx.x;
    const float* src;
    __half* dst;
    if (row < B_ROWS) {
        src = feat + (size_t)row * D_DIM;
        dst = g_f16 + (size_t)row * D_DIM;
    } else {
        row -= B_ROWS;
        src = wts + (size_t)row * D_DIM;
        dst = g_w16 + (size_t)row * D_DIM;
    }
    const int tid = threadIdx.x;
    const float4 v = reinterpret_cast<const float4*>(src)[tid];
    float ss = v.x * v.x + v.y * v.y + v.z * v.z + v.w * v.w;
    #pragma unroll
    for (int o = 16; o; o >>= 1) ss += __shfl_xor_sync(0xFFFFFFFFu, ss, o);
    __shared__ float ws[4];
    if ((tid & 31) == 0) ws[tid >> 5] = ss;
    __syncthreads();
    const float inv = rsqrtf(ws[0] + ws[1] + ws[2] + ws[3]);
    __half2 h0 = __floats2half2_rn(v.x * inv, v.y * inv);
    __half2 h1 = __floats2half2_rn(v.z * inv, v.w * inv);
    uint2 pk;
    pk.x = *reinterpret_cast<uint32_t*>(&h0);
    pk.y = *reinterpret_cast<uint32_t*>(&h1);
    reinterpret_cast<uint2*>(dst)[tid] = pk;
}

// ---------------------------------------------------------------------------
// ArcFace margin for the label column
// ---------------------------------------------------------------------------
__device__ __forceinline__ float af_margin(float c) {
    if (c > AF_THRESH) {
        float s = sqrtf(fmaxf(0.0f, 1.0f - c * c));
        return AF_SCALE * (c * AF_COSM - s * AF_SINM);
    }
    return AF_SCALE * (c + AF_EXTV);
}

// ---------------------------------------------------------------------------
// GEMM tile body: 128x128 CTA tile, 8 warps as 2m x 4n (warp tile 64x32),
// 3-stage cp.async pipeline, 2 CTAs/SM (16 warps), fp32 accumulators.
// KEY CHANGE vs R12: ks-phase rotation at the CORRECT granularity.
// The 4 warps resident on one SMSP are {CTA0:w, CTA0:w+4, CTA1:w, CTA1:w+4}
// (same wid&3!), so R12's (wid&3) rotation left them in lock-step. Rotating
// by (wid>>2) + 2*CTA-parity gives same-SMSP warps distinct ks phases, so
// at any instant some warps feed the tensor pipe while others use the smem
// crossbar — breaking the measured ~100% serialization of the two pipes.
// Accumulation over k is commutative -> identical results.
// ---------------------------------------------------------------------------
template <bool FULL>
__device__ __forceinline__ void gemm_tile(const int* __restrict__ label,
                                          float* __restrict__ cos_out,
                                          float* __restrict__ marg_out,
                                          uint32_t sbase, int m0, int n0,
                                          int cta_par) {
    const int tid  = threadIdx.x;
    const int lane = tid & 31;
    const int wid  = tid >> 5;
    const int warp_m = wid & 1;     // 0..1  (64-row slab)
    const int warp_n = wid >> 1;    // 0..3  (32-col slab)

    // ---- loader bases (per thread) ----
    const int c16 = tid & 7;
    const int rq  = tid >> 3;
    const uint32_t dA = sbase + (uint32_t)(rq * 128 + ((c16 * 16) ^ ((rq & 7) << 4)));
    const uint32_t dB = dA + 16384;

    const __half* aSrc = g_f16 + (size_t)(m0 + rq) * D_DIM + c16 * 8;
    const __half* bSrc = nullptr;
    const __half* bSrcT[4];
    uint32_t bSz[4];
    if constexpr (FULL) {
        bSrc = g_w16 + (size_t)(n0 + rq) * D_DIM + c16 * 8;
    } else {
        #pragma unroll
        for (int i = 0; i < 4; i++) {
            int n = n0 + rq + i * 32;
            bSrcT[i] = g_w16 + (size_t)((n < C_DIM) ? n : 0) * D_DIM + c16 * 8;
            bSz[i]   = (n < C_DIM) ? 16u : 0u;
        }
    }

    // ---- ldmatrix: phase-rotated ks order ----
    const uint32_t col0 =
        ((uint32_t)((lane >> 4) * 16)) ^ ((uint32_t)((lane & 7) << 4));
    const int ks0 = ((wid >> 2) + 2 * cta_par) & 3;   // distinct per SMSP-warp
    uint32_t col_swz[4];       // col_swz[s] = column for ks = (ks0 + s) & 3
    #pragma unroll
    for (int s = 0; s < 4; s++)
        col_swz[s] = col0 ^ (uint32_t)((((ks0 + s) & 3)) << 5);
    const uint32_t a_row = sbase + (uint32_t)((warp_m * 64 + (lane & 15)) * 128);
    const uint32_t b_row = sbase + 16384u + (uint32_t)((warp_n * 32 + (lane & 15)) * 128);

    float acc[4][4][4];
    #pragma unroll
    for (int mt = 0; mt < 4; mt++)
        #pragma unroll
        for (int nt = 0; nt < 4; nt++)
            #pragma unroll
            for (int e = 0; e < 4; e++) acc[mt][nt][e] = 0.0f;

    auto load_stage = [&](int st, int kk) {
        #pragma unroll
        for (int i = 0; i < 4; i++)
            cp16(dA + st * STAGE_BYTES + i * 4096, aSrc + kk + i * 16384);
        #pragma unroll
        for (int i = 0; i < 4; i++) {
            if constexpr (FULL)
                cp16(dB + st * STAGE_BYTES + i * 4096, bSrc + kk + i * 16384);
            else
                cp16z(dB + st * STAGE_BYTES + i * 4096, bSrcT[i] + kk, bSz[i]);
        }
    };

    // prologue: stages 0,1
    load_stage(0, 0);  CP_COMMIT();
    load_stage(1, BK); CP_COMMIT();

    #pragma unroll
    for (int k = 0; k < NK; k++) {
        CP_WAIT(1);
        __syncthreads();

        if (k + 2 < NK) load_stage((k + 2) % STAGES, (k + 2) * BK);
        CP_COMMIT();   // empty group in drain iters keeps wait count uniform

        const int st = (k % STAGES) * STAGE_BYTES;   // immediate under unroll
        const uint32_t aB = a_row + st;
        const uint32_t bB = b_row + st;

        #pragma unroll
        for (int s = 0; s < 4; s++) {          // warp-local ks = (ks0+s)&3
            const uint32_t c = col_swz[s];
            uint32_t a_frag[4][4];
            #pragma unroll
            for (int mt = 0; mt < 4; mt++)
                LDSM_X4(a_frag[mt], aB + c + mt * 2048);
            uint32_t b_frag[2][4];
            #pragma unroll
            for (int g = 0; g < 2; g++)
                LDSM_X4(b_frag[g], bB + c + g * 2048);
            #pragma unroll
            for (int mt = 0; mt < 4; mt++)
                #pragma unroll
                for (int nt = 0; nt < 4; nt++) {
                    int g = nt >> 1, w = nt & 1;
                    mma_16816(acc[mt][nt], a_frag[mt],
                              b_frag[g][w], b_frag[g][w + 2]);
                }
        }
    }

    // --- fused epilogue: cos + ArcFace marginal logits, streaming stores ---
    const int mrow  = m0 + warp_m * 64 + (lane >> 2);
    const int ncol0 = n0 + warp_n * 32 + (lane & 3) * 2;
    #pragma unroll
    for (int mt = 0; mt < 4; mt++) {
        const int m1 = mrow + mt * 16;
        const int m2 = m1 + 8;
        const int lab1 = label[m1];
        const int lab2 = label[m2];
        #pragma unroll
        for (int nt = 0; nt < 4; nt++) {
            int n = ncol0 + nt * 8;
            if (!FULL && n >= C_DIM) continue;
            float c0 = acc[mt][nt][0], c1 = acc[mt][nt][1];
            float c2 = acc[mt][nt][2], c3 = acc[mt][nt][3];
            size_t o1 = (size_t)m1 * C_DIM + n;
            size_t o2 = (size_t)m2 * C_DIM + n;
            st_cs_f2(cos_out + o1, c0, c1);
            st_cs_f2(cos_out + o2, c2, c3);
            float g0 = (n     == lab1) ? af_margin(c0) : AF_SCALE * c0;
            float g1 = (n + 1 == lab1) ? af_margin(c1) : AF_SCALE * c1;
            float g2 = (n     == lab2) ? af_margin(c2) : AF_SCALE * c2;
            float g3 = (n + 1 == lab2) ? af_margin(c3) : AF_SCALE * c3;
            st_cs_f2(marg_out + o1, g0, g1);
            st_cs_f2(marg_out + o2, g2, g3);
        }
    }
}

__global__ void __launch_bounds__(THREADS, 2)
arcface_gemm_kernel(const int* __restrict__ label,
                    float* __restrict__ cos_out, float* __restrict__ marg_out) {
    extern __shared__ char dsmem[];
    const uint32_t sbase = (smem_u32(dsmem) + 1023u) & ~1023u;
    const int n0 = blockIdx.x * BN;
    const int m0 = blockIdx.y * BM;
    const int cta_par = (blockIdx.x ^ blockIdx.y) & 1;
    if (n0 + BN <= C_DIM)
        gemm_tile<true>(label, cos_out, marg_out, sbase, m0, n0, cta_par);
    else
        gemm_tile<false>(label, cos_out, marg_out, sbase, m0, n0, cta_par);
}

// ---------------------------------------------------------------------------
// Launch
// ---------------------------------------------------------------------------
extern "C" void kernel_launch(void* const* d_in, const int* in_sizes, int n_in,
                              void* d_out, int out_size) {
    const float* feat  = (const float*)d_in[0];
    const int*   label = (const int*)d_in[1];
    const float* wts   = (const float*)d_in[2];
    float* cos_out  = (float*)d_out;
    float* marg_out = cos_out + (size_t)B_ROWS * C_DIM;

    norm_rows_kernel<<<B_ROWS + C_DIM, 128>>>(feat, wts);

    cudaFuncSetAttribute(arcface_gemm_kernel,
                         cudaFuncAttributeMaxDynamicSharedMemorySize,
                         SMEM_BYTES);

    dim3 grid((C_DIM + BN - 1) / BN, B_ROWS / BM);   // (157, 32)
    arcface_gemm_kernel<<<grid, THREADS, SMEM_BYTES>>>(label, cos_out, marg_out);
}

// round 15
// speedup vs baseline: 1.2683x; 1.0037x over previous
#include <cuda_runtime.h>
#include <cuda_fp16.h>
#include <cstdint>

// ---------------------------------------------------------------------------
// Problem constants
// ---------------------------------------------------------------------------
#define B_ROWS 4096
#define D_DIM  512
#define C_DIM  20000

#define BM 128
#define BN 128
#define BK 64                   // 64 fp16 = 128B rows (SW128 atom)
#define NK (D_DIM / BK)         // 8 k-iterations
#define STAGES 3
#define THREADS 256

#define STAGE_BYTES ((BM + BN) * BK * 2)   // 32768
#define SMEM_BYTES  (STAGES * STAGE_BYTES + 1024)

static __device__ __half g_f16[(size_t)B_ROWS * D_DIM];   // normalized feat, fp16
static __device__ __half g_w16[(size_t)C_DIM * D_DIM];    // normalized weights, fp16

// ArcFace constants
#define AF_SCALE  30.0f
#define AF_COSM   0.87758256189037271612f   // cos(0.5)
#define AF_SINM   0.47942553860420300027f   // sin(0.5)
#define AF_THRESH (-0.87758256189037271612f)
#define AF_EXTV   (-0.23971276930210150013f) // -0.5*sin(0.5)

// ---------------------------------------------------------------------------
// PTX helpers
// ---------------------------------------------------------------------------
__device__ __forceinline__ uint32_t smem_u32(const void* p) {
    uint32_t a;
    asm("{ .reg .u64 t; cvta.to.shared.u64 t, %1; cvt.u32.u64 %0, t; }"
        : "=r"(a) : "l"(p));
    return a;
}

__device__ __forceinline__ void cp16(uint32_t dst, const void* src) {
    asm volatile("cp.async.cg.shared.global [%0], [%1], 16;"
                 :: "r"(dst), "l"(src));
}
__device__ __forceinline__ void cp16z(uint32_t dst, const void* src,
                                      uint32_t ssize) {
    asm volatile("cp.async.cg.shared.global [%0], [%1], 16, %2;"
                 :: "r"(dst), "l"(src), "r"(ssize));
}
#define CP_COMMIT() asm volatile("cp.async.commit_group;" ::: "memory")
#define CP_WAIT(n)  asm volatile("cp.async.wait_group %0;" :: "n"(n) : "memory")

#define LDSM_X4(r, addr) \
    asm volatile("ldmatrix.sync.aligned.m8n8.x4.shared.b16 {%0,%1,%2,%3}, [%4];" \
        : "=r"((r)[0]), "=r"((r)[1]), "=r"((r)[2]), "=r"((r)[3]) : "r"(addr))

__device__ __forceinline__ void mma_16816(float* d, const uint32_t* a,
                                          uint32_t b0, uint32_t b1) {
    asm volatile(
        "mma.sync.aligned.m16n8k16.row.col.f32.f16.f16.f32 "
        "{%0,%1,%2,%3}, {%4,%5,%6,%7}, {%8,%9}, {%0,%1,%2,%3};"
        : "+f"(d[0]), "+f"(d[1]), "+f"(d[2]), "+f"(d[3])
        : "r"(a[0]), "r"(a[1]), "r"(a[2]), "r"(a[3]), "r"(b0), "r"(b1));
}

__device__ __forceinline__ void st_cs_f2(float* p, float x, float y) {
    asm volatile("st.global.cs.v2.f32 [%0], {%1, %2};"
                 :: "l"(p), "f"(x), "f"(y) : "memory");
}

// ---------------------------------------------------------------------------
// Kernel 1: row L2-normalize fp32 -> fp16; 2 rows per 256-thread block.
// ---------------------------------------------------------------------------
__global__ void __launch_bounds__(256)
norm_rows_kernel(const float* __restrict__ feat,
                 const float* __restrict__ wts) {
    const int half = threadIdx.x >> 7;            // 0 or 1: which row
    const int tid  = threadIdx.x & 127;
    int row = blockIdx.x * 2 + half;
    const float* src;
    __half* dst;
    if (row < B_ROWS) {
        src = feat + (size_t)row * D_DIM;
        dst = g_f16 + (size_t)row * D_DIM;
    } else {
        row -= B_ROWS;
        src = wts + (size_t)row * D_DIM;
        dst = g_w16 + (size_t)row * D_DIM;
    }
    const float4 v = reinterpret_cast<const float4*>(src)[tid];
    float ss = v.x * v.x + v.y * v.y + v.z * v.z + v.w * v.w;
    #pragma unroll
    for (int o = 16; o; o >>= 1) ss += __shfl_xor_sync(0xFFFFFFFFu, ss, o);
    __shared__ float ws[8];
    if ((tid & 31) == 0) ws[half * 4 + (tid >> 5)] = ss;
    __syncthreads();
    const float inv = rsqrtf(ws[half * 4 + 0] + ws[half * 4 + 1] +
                             ws[half * 4 + 2] + ws[half * 4 + 3]);
    __half2 h0 = __floats2half2_rn(v.x * inv, v.y * inv);
    __half2 h1 = __floats2half2_rn(v.z * inv, v.w * inv);
    uint2 pk;
    pk.x = *reinterpret_cast<uint32_t*>(&h0);
    pk.y = *reinterpret_cast<uint32_t*>(&h1);
    reinterpret_cast<uint2*>(dst)[tid] = pk;
}

// ---------------------------------------------------------------------------
// ArcFace margin for the label column
// ---------------------------------------------------------------------------
__device__ __forceinline__ float af_margin(float c) {
    if (c > AF_THRESH) {
        float s = sqrtf(fmaxf(0.0f, 1.0f - c * c));
        return AF_SCALE * (c * AF_COSM - s * AF_SINM);
    }
    return AF_SCALE * (c + AF_EXTV);
}

// ---------------------------------------------------------------------------
// GEMM tile body (R8 mainloop — best measured, 98% of the HMMA-rate wall):
// 128x128 CTA tile, 8 warps as 2m x 4n (warp tile 64x32), 3-stage cp.async,
// 2 CTAs/SM, fp32 accumulators, fragment double-buffering across ks.
// ---------------------------------------------------------------------------
template <bool FULL>
__device__ __forceinline__ void gemm_tile(const int* __restrict__ label,
                                          float* __restrict__ cos_out,
                                          float* __restrict__ marg_out,
                                          uint32_t sbase, int m0, int n0) {
    const int tid  = threadIdx.x;
    const int lane = tid & 31;
    const int wid  = tid >> 5;
    const int warp_m = wid & 1;     // 0..1  (64-row slab)
    const int warp_n = wid >> 1;    // 0..3  (32-col slab)

    // ---- loader bases (per thread) ----
    const int c16 = tid & 7;
    const int rq  = tid >> 3;
    const uint32_t dA = sbase + (uint32_t)(rq * 128 + ((c16 * 16) ^ ((rq & 7) << 4)));
    const uint32_t dB = dA + 16384;

    const __half* aSrc = g_f16 + (size_t)(m0 + rq) * D_DIM + c16 * 8;
    const __half* bSrc = nullptr;
    const __half* bSrcT[4];
    uint32_t bSz[4];
    if constexpr (FULL) {
        bSrc = g_w16 + (size_t)(n0 + rq) * D_DIM + c16 * 8;
    } else {
        #pragma unroll
        for (int i = 0; i < 4; i++) {
            int n = n0 + rq + i * 32;
            bSrcT[i] = g_w16 + (size_t)((n < C_DIM) ? n : 0) * D_DIM + c16 * 8;
            bSz[i]   = (n < C_DIM) ? 16u : 0u;
        }
    }

    // ---- ldmatrix bases (XOR-derived per-ks column) ----
    const uint32_t col0 =
        ((uint32_t)((lane >> 4) * 16)) ^ ((uint32_t)((lane & 7) << 4));
    const uint32_t a_row = sbase + (uint32_t)((warp_m * 64 + (lane & 15)) * 128);
    const uint32_t b_row = sbase + 16384u + (uint32_t)((warp_n * 32 + (lane & 15)) * 128);

    float acc[4][4][4];
    #pragma unroll
    for (int mt = 0; mt < 4; mt++)
        #pragma unroll
        for (int nt = 0; nt < 4; nt++)
            #pragma unroll
            for (int e = 0; e < 4; e++) acc[mt][nt][e] = 0.0f;

    auto load_stage = [&](int st, int kk) {
        #pragma unroll
        for (int i = 0; i < 4; i++)
            cp16(dA + st * STAGE_BYTES + i * 4096, aSrc + kk + i * 16384);
        #pragma unroll
        for (int i = 0; i < 4; i++) {
            if constexpr (FULL)
                cp16(dB + st * STAGE_BYTES + i * 4096, bSrc + kk + i * 16384);
            else
                cp16z(dB + st * STAGE_BYTES + i * 4096, bSrcT[i] + kk, bSz[i]);
        }
    };

    // prologue: stages 0,1
    load_stage(0, 0);  CP_COMMIT();
    load_stage(1, BK); CP_COMMIT();

    // double-buffered fragment sets
    uint32_t afr[2][4][4];
    uint32_t bfr[2][2][4];

    #pragma unroll
    for (int k = 0; k < NK; k++) {
        CP_WAIT(1);
        __syncthreads();

        const int st = (k % STAGES) * STAGE_BYTES;   // immediate under unroll
        const uint32_t aB = a_row + st;
        const uint32_t bB = b_row + st;

        // preload ks=0 fragments
        {
            const uint32_t c = col0;
            #pragma unroll
            for (int mt = 0; mt < 4; mt++)
                LDSM_X4(afr[0][mt], aB + c + mt * 2048);
            #pragma unroll
            for (int g = 0; g < 2; g++)
                LDSM_X4(bfr[0][g], bB + c + g * 2048);
        }

        // issue next-stage global prefetch while frags are in flight
        if (k + 2 < NK) load_stage((k + 2) % STAGES, (k + 2) * BK);
        CP_COMMIT();   // empty group in drain iters keeps wait count uniform

        #pragma unroll
        for (int ks = 0; ks < 4; ks++) {
            const int cur = ks & 1;
            if (ks < 3) {
                const int nxt = cur ^ 1;
                const uint32_t c = col0 ^ (uint32_t)((ks + 1) << 5);
                #pragma unroll
                for (int mt = 0; mt < 4; mt++)
                    LDSM_X4(afr[nxt][mt], aB + c + mt * 2048);
                #pragma unroll
                for (int g = 0; g < 2; g++)
                    LDSM_X4(bfr[nxt][g], bB + c + g * 2048);
            }
            #pragma unroll
            for (int mt = 0; mt < 4; mt++)
                #pragma unroll
                for (int nt = 0; nt < 4; nt++) {
                    int g = nt >> 1, w = nt & 1;
                    mma_16816(acc[mt][nt], afr[cur][mt],
                              bfr[cur][g][w], bfr[cur][g][w + 2]);
                }
        }
    }

    // --- fused epilogue: cos + ArcFace marginal logits, streaming stores ---
    const int mrow  = m0 + warp_m * 64 + (lane >> 2);
    const int ncol0 = n0 + warp_n * 32 + (lane & 3) * 2;
    #pragma unroll
    for (int mt = 0; mt < 4; mt++) {
        const int m1 = mrow + mt * 16;
        const int m2 = m1 + 8;
        const int lab1 = label[m1];
        const int lab2 = label[m2];
        #pragma unroll
        for (int nt = 0; nt < 4; nt++) {
            int n = ncol0 + nt * 8;
            if (!FULL && n >= C_DIM) continue;
            float c0 = acc[mt][nt][0], c1 = acc[mt][nt][1];
            float c2 = acc[mt][nt][2], c3 = acc[mt][nt][3];
            size_t o1 = (size_t)m1 * C_DIM + n;
            size_t o2 = (size_t)m2 * C_DIM + n;
            st_cs_f2(cos_out + o1, c0, c1);
            st_cs_f2(cos_out + o2, c2, c3);
            float g0 = (n     == lab1) ? af_margin(c0) : AF_SCALE * c0;
            float g1 = (n + 1 == lab1) ? af_margin(c1) : AF_SCALE * c1;
            float g2 = (n     == lab2) ? af_margin(c2) : AF_SCALE * c2;
            float g3 = (n + 1 == lab2) ? af_margin(c3) : AF_SCALE * c3;
            st_cs_f2(marg_out + o1, g0, g1);
            st_cs_f2(marg_out + o2, g2, g3);
        }
    }
}

__global__ void __launch_bounds__(THREADS, 2)
arcface_gemm_kernel(const int* __restrict__ label,
                    float* __restrict__ cos_out, float* __restrict__ marg_out) {
    extern __shared__ char dsmem[];
    const uint32_t sbase = (smem_u32(dsmem) + 1023u) & ~1023u;
    const int n0 = blockIdx.x * BN;
    const int m0 = blockIdx.y * BM;
    if (n0 + BN <= C_DIM)
        gemm_tile<true>(label, cos_out, marg_out, sbase, m0, n0);
    else
        gemm_tile<false>(label, cos_out, marg_out, sbase, m0, n0);
}

// ---------------------------------------------------------------------------
// Launch
// ---------------------------------------------------------------------------
extern "C" void kernel_launch(void* const* d_in, const int* in_sizes, int n_in,
                              void* d_out, int out_size) {
    const float* feat  = (const float*)d_in[0];
    const int*   label = (const int*)d_in[1];
    const float* wts   = (const float*)d_in[2];
    float* cos_out  = (float*)d_out;
    float* marg_out = cos_out + (size_t)B_ROWS * C_DIM;

    norm_rows_kernel<<<(B_ROWS + C_DIM) / 2, 256>>>(feat, wts);

    cudaFuncSetAttribute(arcface_gemm_kernel,
                         cudaFuncAttributeMaxDynamicSharedMemorySize,
                         SMEM_BYTES);

    dim3 grid((C_DIM + BN - 1) / BN, B_ROWS / BM);   // (157, 32)
    arcface_gemm_kernel<<<grid, THREADS, SMEM_BYTES>>>(label, cos_out, marg_out);
}

// round 16
// speedup vs baseline: 1.2899x; 1.0170x over previous
#include <cuda_runtime.h>
#include <cuda_fp16.h>
#include <cstdint>

// ---------------------------------------------------------------------------
// Problem constants
// ---------------------------------------------------------------------------
#define B_ROWS 4096
#define D_DIM  512
#define C_DIM  20000

#define BM 128
#define BN 128
#define BK 64                   // 64 fp16 = 128B rows (SW128 atom)
#define NK (D_DIM / BK)         // 8 k-iterations
#define STAGES 3
#define THREADS 256

#define STAGE_BYTES ((BM + BN) * BK * 2)   // 32768
#define SMEM_BYTES  (STAGES * STAGE_BYTES + 1024)

static __device__ __half g_f16[(size_t)B_ROWS * D_DIM];   // normalized feat, fp16
static __device__ __half g_w16[(size_t)C_DIM * D_DIM];    // normalized weights, fp16

// ArcFace constants
#define AF_SCALE  30.0f
#define AF_COSM   0.87758256189037271612f   // cos(0.5)
#define AF_SINM   0.47942553860420300027f   // sin(0.5)
#define AF_THRESH (-0.87758256189037271612f)
#define AF_EXTV   (-0.23971276930210150013f) // -0.5*sin(0.5)

// ---------------------------------------------------------------------------
// PTX helpers
// ---------------------------------------------------------------------------
__device__ __forceinline__ uint32_t smem_u32(const void* p) {
    uint32_t a;
    asm("{ .reg .u64 t; cvta.to.shared.u64 t, %1; cvt.u32.u64 %0, t; }"
        : "=r"(a) : "l"(p));
    return a;
}

__device__ __forceinline__ void cp16(uint32_t dst, const void* src) {
    asm volatile("cp.async.cg.shared.global [%0], [%1], 16;"
                 :: "r"(dst), "l"(src));
}
__device__ __forceinline__ void cp16z(uint32_t dst, const void* src,
                                      uint32_t ssize) {
    asm volatile("cp.async.cg.shared.global [%0], [%1], 16, %2;"
                 :: "r"(dst), "l"(src), "r"(ssize));
}
#define CP_COMMIT() asm volatile("cp.async.commit_group;" ::: "memory")
#define CP_WAIT(n)  asm volatile("cp.async.wait_group %0;" :: "n"(n) : "memory")

#define LDSM_X4(r, addr) \
    asm volatile("ldmatrix.sync.aligned.m8n8.x4.shared.b16 {%0,%1,%2,%3}, [%4];" \
        : "=r"((r)[0]), "=r"((r)[1]), "=r"((r)[2]), "=r"((r)[3]) : "r"(addr))

__device__ __forceinline__ void mma_16816(float* d, const uint32_t* a,
                                          uint32_t b0, uint32_t b1) {
    asm volatile(
        "mma.sync.aligned.m16n8k16.row.col.f32.f16.f16.f32 "
        "{%0,%1,%2,%3}, {%4,%5,%6,%7}, {%8,%9}, {%0,%1,%2,%3};"
        : "+f"(d[0]), "+f"(d[1]), "+f"(d[2]), "+f"(d[3])
        : "r"(a[0]), "r"(a[1]), "r"(a[2]), "r"(a[3]), "r"(b0), "r"(b1));
}

__device__ __forceinline__ void st_cs_f2(float* p, float x, float y) {
    asm volatile("st.global.cs.v2.f32 [%0], {%1, %2};"
                 :: "l"(p), "f"(x), "f"(y) : "memory");
}

// ---------------------------------------------------------------------------
// Kernel 1: row L2-normalize fp32 -> fp16, warp-per-row (no smem, no barrier).
// Each lane: 4 float4 loads (MLP=4), shfl-xor reduce, 4 uint2 stores.
// 16 rows per 512-thread block -> 1506 blocks for all 24096 rows.
// ---------------------------------------------------------------------------
__global__ void __launch_bounds__(512)
norm_rows_kernel(const float* __restrict__ feat,
                 const float* __restrict__ wts) {
    const int lane = threadIdx.x & 31;
    int row = blockIdx.x * 16 + (threadIdx.x >> 5);
    const float* src;
    __half* dst;
    if (row < B_ROWS) {
        src = feat + (size_t)row * D_DIM;
        dst = g_f16 + (size_t)row * D_DIM;
    } else {
        row -= B_ROWS;
        if (row >= C_DIM) return;
        src = wts + (size_t)row * D_DIM;
        dst = g_w16 + (size_t)row * D_DIM;
    }

    float4 v[4];
    const float4* p = reinterpret_cast<const float4*>(src);
    #pragma unroll
    for (int i = 0; i < 4; i++) v[i] = p[lane + i * 32];

    float ss = 0.0f;
    #pragma unroll
    for (int i = 0; i < 4; i++)
        ss += v[i].x * v[i].x + v[i].y * v[i].y +
              v[i].z * v[i].z + v[i].w * v[i].w;
    #pragma unroll
    for (int o = 16; o; o >>= 1) ss += __shfl_xor_sync(0xFFFFFFFFu, ss, o);

    const float inv = rsqrtf(ss);
    uint2* q = reinterpret_cast<uint2*>(dst);
    #pragma unroll
    for (int i = 0; i < 4; i++) {
        __half2 h0 = __floats2half2_rn(v[i].x * inv, v[i].y * inv);
        __half2 h1 = __floats2half2_rn(v[i].z * inv, v[i].w * inv);
        uint2 pk;
        pk.x = *reinterpret_cast<uint32_t*>(&h0);
        pk.y = *reinterpret_cast<uint32_t*>(&h1);
        q[lane + i * 32] = pk;
    }
}

// ---------------------------------------------------------------------------
// ArcFace margin for the label column
// ---------------------------------------------------------------------------
__device__ __forceinline__ float af_margin(float c) {
    if (c > AF_THRESH) {
        float s = sqrtf(fmaxf(0.0f, 1.0f - c * c));
        return AF_SCALE * (c * AF_COSM - s * AF_SINM);
    }
    return AF_SCALE * (c + AF_EXTV);
}

// ---------------------------------------------------------------------------
// GEMM tile body (R15 mainloop, UNCHANGED — measured at 284.6us, ~98% of the
// legacy-HMMA instruction-rate wall): 128x128 CTA tile, 8 warps as 2m x 4n,
// 3-stage cp.async, 2 CTAs/SM, fp32 accumulators, fragment double-buffering.
// ---------------------------------------------------------------------------
template <bool FULL>
__device__ __forceinline__ void gemm_tile(const int* __restrict__ label,
                                          float* __restrict__ cos_out,
                                          float* __restrict__ marg_out,
                                          uint32_t sbase, int m0, int n0) {
    const int tid  = threadIdx.x;
    const int lane = tid & 31;
    const int wid  = tid >> 5;
    const int warp_m = wid & 1;     // 0..1  (64-row slab)
    const int warp_n = wid >> 1;    // 0..3  (32-col slab)

    // ---- loader bases (per thread) ----
    const int c16 = tid & 7;
    const int rq  = tid >> 3;
    const uint32_t dA = sbase + (uint32_t)(rq * 128 + ((c16 * 16) ^ ((rq & 7) << 4)));
    const uint32_t dB = dA + 16384;

    const __half* aSrc = g_f16 + (size_t)(m0 + rq) * D_DIM + c16 * 8;
    const __half* bSrc = nullptr;
    const __half* bSrcT[4];
    uint32_t bSz[4];
    if constexpr (FULL) {
        bSrc = g_w16 + (size_t)(n0 + rq) * D_DIM + c16 * 8;
    } else {
        #pragma unroll
        for (int i = 0; i < 4; i++) {
            int n = n0 + rq + i * 32;
            bSrcT[i] = g_w16 + (size_t)((n < C_DIM) ? n : 0) * D_DIM + c16 * 8;
            bSz[i]   = (n < C_DIM) ? 16u : 0u;
        }
    }

    // ---- ldmatrix bases (XOR-derived per-ks column) ----
    const uint32_t col0 =
        ((uint32_t)((lane >> 4) * 16)) ^ ((uint32_t)((lane & 7) << 4));
    const uint32_t a_row = sbase + (uint32_t)((warp_m * 64 + (lane & 15)) * 128);
    const uint32_t b_row = sbase + 16384u + (uint32_t)((warp_n * 32 + (lane & 15)) * 128);

    float acc[4][4][4];
    #pragma unroll
    for (int mt = 0; mt < 4; mt++)
        #pragma unroll
        for (int nt = 0; nt < 4; nt++)
            #pragma unroll
            for (int e = 0; e < 4; e++) acc[mt][nt][e] = 0.0f;

    auto load_stage = [&](int st, int kk) {
        #pragma unroll
        for (int i = 0; i < 4; i++)
            cp16(dA + st * STAGE_BYTES + i * 4096, aSrc + kk + i * 16384);
        #pragma unroll
        for (int i = 0; i < 4; i++) {
            if constexpr (FULL)
                cp16(dB + st * STAGE_BYTES + i * 4096, bSrc + kk + i * 16384);
            else
                cp16z(dB + st * STAGE_BYTES + i * 4096, bSrcT[i] + kk, bSz[i]);
        }
    };

    // prologue: stages 0,1
    load_stage(0, 0);  CP_COMMIT();
    load_stage(1, BK); CP_COMMIT();

    // double-buffered fragment sets
    uint32_t afr[2][4][4];
    uint32_t bfr[2][2][4];

    #pragma unroll
    for (int k = 0; k < NK; k++) {
        CP_WAIT(1);
        __syncthreads();

        const int st = (k % STAGES) * STAGE_BYTES;   // immediate under unroll
        const uint32_t aB = a_row + st;
        const uint32_t bB = b_row + st;

        // preload ks=0 fragments
        {
            const uint32_t c = col0;
            #pragma unroll
            for (int mt = 0; mt < 4; mt++)
                LDSM_X4(afr[0][mt], aB + c + mt * 2048);
            #pragma unroll
            for (int g = 0; g < 2; g++)
                LDSM_X4(bfr[0][g], bB + c + g * 2048);
        }

        // issue next-stage global prefetch while frags are in flight
        if (k + 2 < NK) load_stage((k + 2) % STAGES, (k + 2) * BK);
        CP_COMMIT();   // empty group in drain iters keeps wait count uniform

        #pragma unroll
        for (int ks = 0; ks < 4; ks++) {
            const int cur = ks & 1;
            if (ks < 3) {
                const int nxt = cur ^ 1;
                const uint32_t c = col0 ^ (uint32_t)((ks + 1) << 5);
                #pragma unroll
                for (int mt = 0; mt < 4; mt++)
                    LDSM_X4(afr[nxt][mt], aB + c + mt * 2048);
                #pragma unroll
                for (int g = 0; g < 2; g++)
                    LDSM_X4(bfr[nxt][g], bB + c + g * 2048);
            }
            #pragma unroll
            for (int mt = 0; mt < 4; mt++)
                #pragma unroll
                for (int nt = 0; nt < 4; nt++) {
                    int g = nt >> 1, w = nt & 1;
                    mma_16816(acc[mt][nt], afr[cur][mt],
                              bfr[cur][g][w], bfr[cur][g][w + 2]);
                }
        }
    }

    // --- fused epilogue: cos + ArcFace marginal logits, streaming stores ---
    const int mrow  = m0 + warp_m * 64 + (lane >> 2);
    const int ncol0 = n0 + warp_n * 32 + (lane & 3) * 2;
    #pragma unroll
    for (int mt = 0; mt < 4; mt++) {
        const int m1 = mrow + mt * 16;
        const int m2 = m1 + 8;
        const int lab1 = label[m1];
        const int lab2 = label[m2];
        #pragma unroll
        for (int nt = 0; nt < 4; nt++) {
            int n = ncol0 + nt * 8;
            if (!FULL && n >= C_DIM) continue;
            float c0 = acc[mt][nt][0], c1 = acc[mt][nt][1];
            float c2 = acc[mt][nt][2], c3 = acc[mt][nt][3];
            size_t o1 = (size_t)m1 * C_DIM + n;
            size_t o2 = (size_t)m2 * C_DIM + n;
            st_cs_f2(cos_out + o1, c0, c1);
            st_cs_f2(cos_out + o2, c2, c3);
            float g0 = (n     == lab1) ? af_margin(c0) : AF_SCALE * c0;
            float g1 = (n + 1 == lab1) ? af_margin(c1) : AF_SCALE * c1;
            float g2 = (n     == lab2) ? af_margin(c2) : AF_SCALE * c2;
            float g3 = (n + 1 == lab2) ? af_margin(c3) : AF_SCALE * c3;
            st_cs_f2(marg_out + o1, g0, g1);
            st_cs_f2(marg_out + o2, g2, g3);
        }
    }
}

__global__ void __launch_bounds__(THREADS, 2)
arcface_gemm_kernel(const int* __restrict__ label,
                    float* __restrict__ cos_out, float* __restrict__ marg_out) {
    extern __shared__ char dsmem[];
    const uint32_t sbase = (smem_u32(dsmem) + 1023u) & ~1023u;
    const int n0 = blockIdx.x * BN;
    const int m0 = blockIdx.y * BM;
    if (n0 + BN <= C_DIM)
        gemm_tile<true>(label, cos_out, marg_out, sbase, m0, n0);
    else
        gemm_tile<false>(label, cos_out, marg_out, sbase, m0, n0);
}

// ---------------------------------------------------------------------------
// Launch
// ---------------------------------------------------------------------------
extern "C" void kernel_launch(void* const* d_in, const int* in_sizes, int n_in,
                              void* d_out, int out_size) {
    const float* feat  = (const float*)d_in[0];
    const int*   label = (const int*)d_in[1];
    const float* wts   = (const float*)d_in[2];
    float* cos_out  = (float*)d_out;
    float* marg_out = cos_out + (size_t)B_ROWS * C_DIM;

    // 24096 rows, 16 rows per 512-thread block
    norm_rows_kernel<<<(B_ROWS + C_DIM + 15) / 16, 512>>>(feat, wts);

    cudaFuncSetAttribute(arcface_gemm_kernel,
                         cudaFuncAttributeMaxDynamicSharedMemorySize,
                         SMEM_BYTES);

    dim3 grid((C_DIM + BN - 1) / BN, B_ROWS / BM);   // (157, 32)
    arcface_gemm_kernel<<<grid, THREADS, SMEM_BYTES>>>(label, cos_out, marg_out);
}